// round 10
// baseline (speedup 1.0000x reference)
#include <cuda_runtime.h>
#include <cuda_bf16.h>
#include <cuda_fp16.h>
#include <cstdint>

#define IN_DIM 128
#define HID    256
#define NU 100000
#define NI 200000
#define NTILE_U ((NU + 127) / 128)   // 782
#define NTILE_I ((NI + 127) / 128)   // 1563
#define KEXT 384                     // B: [Wh ; Wl ; Wh]

#define P_ELEMS (100000u * 256u)
#define Q_ELEMS (200000u * 256u)
__device__ __half g_tab[2u * (P_ELEMS + Q_ELEMS)];
__device__ __align__(16) __nv_bfloat16 g_wext[4][HID * KEXT];

// ---------------------------------------------------------------------------
__device__ __forceinline__ uint32_t smem_u32(const void* p) {
    uint32_t a;
    asm("{ .reg .u64 t; cvta.to.shared.u64 t, %1; cvt.u32.u64 %0, t; }"
        : "=r"(a) : "l"(p));
    return a;
}
__device__ __forceinline__ uint32_t swz(uint32_t o) { return o ^ ((o >> 3) & 0x70); }
__device__ __forceinline__ uint32_t pack2(float a, float b) {
    __nv_bfloat162 t = __floats2bfloat162_rn(a, b);
    return *(uint32_t*)&t;
}
template <int N>
__device__ __forceinline__ void cpwait() {
    asm volatile("cp.async.wait_group %0;" :: "n"(N) : "memory");
}

// ---------------------------------------------------------------------------
// convW (4 combos in one launch): W-half [128 k][256 n] -> [Wh | Wl | Wh]
// ---------------------------------------------------------------------------
__global__ __launch_bounds__(256)
void convW_kernel(const float* __restrict__ Wc, const float* __restrict__ Wb,
                  __nv_bfloat16* __restrict__ wext) {
    const int combo = blockIdx.y;
    const float* Wsrc = ((combo < 2) ? Wc : Wb) + (size_t)(combo & 1) * IN_DIM * HID;
    __nv_bfloat16* Wext = wext + (size_t)combo * HID * KEXT;
    for (int idx = blockIdx.x * 256 + threadIdx.x; idx < HID * IN_DIM;
         idx += gridDim.x * 256) {
        const int n = idx >> 7, k = idx & 127;
        const float x = Wsrc[(size_t)k * HID + n];
        const __nv_bfloat16 h = __float2bfloat16_rn(x);
        const float l = x - __bfloat162float(h);
        __nv_bfloat16* row = Wext + (size_t)n * KEXT;
        row[k]       = h;
        row[128 + k] = __float2bfloat16_rn(l);
        row[256 + k] = h;
    }
}

// ---------------------------------------------------------------------------
// persistent fused gemm, fp32 A read + in-kernel bf16-split conversion.
// smem: Astage fp32 64KB | Aconv bf16 [Ah|Al] swizzled 64KB | B0 32KB | B1 32KB
// Ah converted at tile top; Al conversion deferred into iter 0 (hidden under
// HMMA drain). A prefetch at it==2 (after Al conversion read Astage).
// ---------------------------------------------------------------------------
#define KC 64
#define SM_STAGE 0
#define SM_ACONV 65536
#define SM_B_OFF (2 * 65536)
#define GEMM_SMEM (SM_B_OFF + 2 * 32768)

__device__ __forceinline__ void ldsm4(uint32_t* r, uint32_t a) {
    asm volatile("ldmatrix.sync.aligned.m8n8.x4.shared.b16 {%0,%1,%2,%3}, [%4];"
                 : "=r"(r[0]), "=r"(r[1]), "=r"(r[2]), "=r"(r[3]) : "r"(a));
}
__device__ __forceinline__ void mma16816(float* d, const uint32_t* a, const uint32_t* b) {
    asm volatile("mma.sync.aligned.m16n8k16.row.col.f32.bf16.bf16.f32 "
                 "{%0,%1,%2,%3}, {%4,%5,%6,%7}, {%8,%9}, {%0,%1,%2,%3};"
                 : "+f"(d[0]), "+f"(d[1]), "+f"(d[2]), "+f"(d[3])
                 : "r"(a[0]), "r"(a[1]), "r"(a[2]), "r"(a[3]), "r"(b[0]), "r"(b[1]));
}

__global__ __launch_bounds__(512, 1)
void gemm_kernel(const float* __restrict__ A, int ntiles, int N,
                 const __nv_bfloat16* __restrict__ W0,
                 const __nv_bfloat16* __restrict__ W1,
                 const float* __restrict__ b1_0, const float* __restrict__ b1_1,
                 __half* __restrict__ P0, __half* __restrict__ P1) {
    extern __shared__ __align__(1024) unsigned char sm[];
    const uint32_t sbase = smem_u32(sm);
    const int tid  = threadIdx.x;
    const int lane = tid & 31;
    const int wid  = tid >> 5;
    const int wm   = wid & 3;
    const int wn   = wid >> 2;

    auto issue_b = [&](int it) {
        const char* Bb = (const char*)((it < 6) ? W0 : W1);
        const int c = it % 6;
        const uint32_t sb = sbase + SM_B_OFF + (uint32_t)(it & 1) * 32768;
        #pragma unroll
        for (int i = 0; i < 4; i++) {
            const int idx = tid + i * 512;
            const int r = idx >> 3, s = idx & 7;
            const size_t go = (size_t)r * (KEXT * 2) + c * (KC * 2) + s * 16;
            const uint32_t so = swz((uint32_t)(r * 128 + s * 16));
            asm volatile("cp.async.cg.shared.global [%0], [%1], 16;"
                         :: "r"(sb + so), "l"(Bb + go) : "memory");
        }
        asm volatile("cp.async.commit_group;" ::: "memory");
    };
    auto issue_a = [&](int t) {
        const float* Ab = A + (size_t)t * 128 * IN_DIM;
        const uint32_t sa = sbase + SM_STAGE;
        #pragma unroll
        for (int i = 0; i < 8; i++) {
            const int idx = tid + i * 512;
            const int r = idx >> 5, s = idx & 31;
            const int rg = t * 128 + r;
            const uint32_t so = (uint32_t)(r * 512 + s * 16);
            if (rg < N) {
                asm volatile("cp.async.cg.shared.global [%0], [%1], 16;"
                             :: "r"(sa + so), "l"((const char*)Ab + (size_t)r * 512 + s * 16)
                             : "memory");
            } else {
                *(uint4*)(sm + SM_STAGE + so) = make_uint4(0, 0, 0, 0);
            }
        }
        asm volatile("cp.async.commit_group;" ::: "memory");
    };
    // Ah only (chunks 0,1)
    auto convert_ah = [&]() {
        #pragma unroll
        for (int i = 0; i < 8; i++) {
            const int idx = tid + i * 512;
            const int r = idx >> 5, c4 = idx & 31;
            float4 v = *(float4*)(sm + SM_STAGE + r * 512 + c4 * 16);
            uint2 uh = { pack2(v.x, v.y), pack2(v.z, v.w) };
            const uint32_t ck  = (uint32_t)(c4 >> 4);
            const uint32_t off = swz((uint32_t)(r * 128 + (c4 & 15) * 8));
            *(uint2*)(sm + SM_ACONV + ck * 16384 + off) = uh;
        }
    };
    // Al (chunks 2,3): residual via bit-level bf16 unpack (no cvt-back)
    auto convert_al = [&]() {
        #pragma unroll
        for (int i = 0; i < 8; i++) {
            const int idx = tid + i * 512;
            const int r = idx >> 5, c4 = idx & 31;
            float4 v = *(float4*)(sm + SM_STAGE + r * 512 + c4 * 16);
            uint32_t uh0 = pack2(v.x, v.y), uh1 = pack2(v.z, v.w);
            float h0 = __uint_as_float(uh0 << 16);
            float h1 = __uint_as_float(uh0 & 0xffff0000u);
            float h2 = __uint_as_float(uh1 << 16);
            float h3 = __uint_as_float(uh1 & 0xffff0000u);
            uint2 ul = { pack2(v.x - h0, v.y - h1), pack2(v.z - h2, v.w - h3) };
            const uint32_t ck  = (uint32_t)(c4 >> 4);
            const uint32_t off = swz((uint32_t)(r * 128 + (c4 & 15) * 8));
            *(uint2*)(sm + SM_ACONV + 32768 + ck * 16384 + off) = ul;
        }
    };

    float acc[2][8][4];
    #pragma unroll
    for (int mt = 0; mt < 2; mt++)
        #pragma unroll
        for (int nt = 0; nt < 8; nt++)
            #pragma unroll
            for (int j = 0; j < 4; j++) acc[mt][nt][j] = 0.f;

    const int t0 = blockIdx.x;
    if (t0 >= ntiles) return;

    issue_a(t0);
    issue_b(0);

    const int amap[6] = {0, 1, 0, 1, 2, 3};

    for (int t = t0; t < ntiles; t += gridDim.x) {
        const int tnext = t + gridDim.x;
        const bool a_iss = (tnext < ntiles);

        cpwait<1>();          // A(t) complete (newest = B(0) of this tile)
        __syncthreads();
        convert_ah();
        __syncthreads();

        #pragma unroll
        for (int it = 0; it < 12; it++) {
            const bool last_all = (it == 11) && !a_iss;
            if (!last_all) issue_b((it + 1) % 12);
            if (it == 2 && a_iss) issue_a(tnext);

            if (last_all)                          cpwait<0>();
            else if ((it == 2 || it == 3) && a_iss) cpwait<2>();
            else                                   cpwait<1>();
            __syncthreads();

            const uint32_t sa = sbase + SM_ACONV + (uint32_t)(amap[it % 6] * 16384);
            const uint32_t sb = sbase + SM_B_OFF + (uint32_t)(it & 1) * 32768;

            #pragma unroll
            for (int ks = 0; ks < KC / 16; ks++) {
                uint32_t af[2][4];
                #pragma unroll
                for (int mt = 0; mt < 2; mt++) {
                    const int row = wm * 32 + mt * 16 + (lane & 15);
                    const uint32_t off = (uint32_t)(row * 128 + ks * 32 + (lane >> 4) * 16);
                    ldsm4(af[mt], sa + swz(off));
                }
                uint32_t bfr[8][2];
                #pragma unroll
                for (int ntp = 0; ntp < 4; ntp++) {
                    const int nrow = wn * 64 + ntp * 16 + ((lane >> 4) << 3) + (lane & 7);
                    const uint32_t off = (uint32_t)(nrow * 128 + ks * 32 + ((lane >> 3) & 1) * 16);
                    uint32_t r4[4];
                    ldsm4(r4, sb + swz(off));
                    bfr[2 * ntp][0] = r4[0]; bfr[2 * ntp][1] = r4[1];
                    bfr[2 * ntp + 1][0] = r4[2]; bfr[2 * ntp + 1][1] = r4[3];
                }
                #pragma unroll
                for (int mt = 0; mt < 2; mt++)
                    #pragma unroll
                    for (int nt = 0; nt < 8; nt++)
                        mma16816(acc[mt][nt], af[mt], bfr[nt]);
            }

            if (it == 0) convert_al();   // hidden under HMMA drain; Al read at it==4
            __syncthreads();

            if (it == 5 || it == 11) {
                __half* Pt = (it == 5) ? P0 : P1;
                const float* b1 = (it == 5) ? b1_0 : b1_1;
                const int rb = t * 128 + wm * 32 + (lane >> 2);
                const int cb = wn * 64 + (lane & 3) * 2;
                #pragma unroll
                for (int mt = 0; mt < 2; mt++) {
                    #pragma unroll
                    for (int hf = 0; hf < 2; hf++) {
                        const int r = rb + mt * 16 + hf * 8;
                        if (r < N) {
                            __half* dst = Pt + (size_t)r * HID + cb;
                            #pragma unroll
                            for (int nt = 0; nt < 8; nt++) {
                                const int c = cb + nt * 8;
                                float a0 = acc[mt][nt][hf * 2]     + __ldg(b1 + c);
                                float a1 = acc[mt][nt][hf * 2 + 1] + __ldg(b1 + c + 1);
                                *(__half2*)(dst + nt * 8) = __floats2half2_rn(a0, a1);
                            }
                        }
                    }
                }
                #pragma unroll
                for (int mt = 0; mt < 2; mt++)
                    #pragma unroll
                    for (int nt = 0; nt < 8; nt++)
                        #pragma unroll
                        for (int j = 0; j < 4; j++) acc[mt][nt][j] = 0.f;
            }
        }
    }
}

// ---------------------------------------------------------------------------
// edge: persistent warps; W2/b2 hoisted into registers; 2 edges per iteration.
// Warps [0, wpt) -> clicks, [wpt, 2*wpt) -> buys.
// ---------------------------------------------------------------------------
__global__ __launch_bounds__(256)
void edge_kernel(const int* __restrict__ uc, const int* __restrict__ vc,
                 const int* __restrict__ ub, const int* __restrict__ vb,
                 const __half* __restrict__ Pc, const __half* __restrict__ Qc,
                 const __half* __restrict__ Pb, const __half* __restrict__ Qb,
                 const float4* __restrict__ W2c, const float* __restrict__ b2c,
                 const float4* __restrict__ W2b, const float* __restrict__ b2b,
                 float* __restrict__ out, int E, int wpt) {
    const int gw   = (blockIdx.x * blockDim.x + threadIdx.x) >> 5;
    const int lane = threadIdx.x & 31;
    const bool buys = (gw >= wpt);
    const int w0 = buys ? gw - wpt : gw;

    const int* uu = buys ? ub : uc;
    const int* vv = buys ? vb : vc;
    const __half* P = buys ? Pb : Pc;
    const __half* Q = buys ? Qb : Qc;
    const float4* W2 = buys ? W2b : W2c;
    float* o = out + (buys ? E : 0);

    float4 wv0 = __ldg(W2 + lane * 2);
    float4 wv1 = __ldg(W2 + lane * 2 + 1);
    const float b2v = __ldg(buys ? b2b : b2c);
    float w[8] = { wv0.x, wv0.y, wv0.z, wv0.w, wv1.x, wv1.y, wv1.z, wv1.w };

    auto dot8 = [&](const uint4& pr, const uint4& qr) -> float {
        const __half2* p2 = (const __half2*)&pr;
        const __half2* q2 = (const __half2*)&qr;
        float a = 0.f;
        #pragma unroll
        for (int i = 0; i < 4; i++) {
            float2 pf = __half22float2(p2[i]);
            float2 qf = __half22float2(q2[i]);
            a = fmaf(fmaxf(pf.x + qf.x, 0.f), w[2 * i],     a);
            a = fmaf(fmaxf(pf.y + qf.y, 0.f), w[2 * i + 1], a);
        }
        return a;
    };

    int e = w0;
    for (; e + wpt < E; e += 2 * wpt) {
        const int u0 = __ldg(uu + e),       v0 = __ldg(vv + e);
        const int u1 = __ldg(uu + e + wpt), v1 = __ldg(vv + e + wpt);
        uint4 pr0 = *(const uint4*)(P + (size_t)u0 * HID + lane * 8);
        uint4 qr0 = *(const uint4*)(Q + (size_t)v0 * HID + lane * 8);
        uint4 pr1 = *(const uint4*)(P + (size_t)u1 * HID + lane * 8);
        uint4 qr1 = *(const uint4*)(Q + (size_t)v1 * HID + lane * 8);
        float a0 = dot8(pr0, qr0);
        float a1 = dot8(pr1, qr1);
        #pragma unroll
        for (int off = 16; off; off >>= 1) {
            a0 += __shfl_xor_sync(0xffffffffu, a0, off);
            a1 += __shfl_xor_sync(0xffffffffu, a1, off);
        }
        if (lane == 0) { o[e] = a0 + b2v; o[e + wpt] = a1 + b2v; }
    }
    if (e < E) {
        const int u0 = __ldg(uu + e), v0 = __ldg(vv + e);
        uint4 pr0 = *(const uint4*)(P + (size_t)u0 * HID + lane * 8);
        uint4 qr0 = *(const uint4*)(Q + (size_t)v0 * HID + lane * 8);
        float a0 = dot8(pr0, qr0);
        #pragma unroll
        for (int off = 16; off; off >>= 1)
            a0 += __shfl_xor_sync(0xffffffffu, a0, off);
        if (lane == 0) o[e] = a0 + b2v;
    }
}

// ---------------------------------------------------------------------------
extern "C" void kernel_launch(void* const* d_in, const int* in_sizes, int n_in,
                              void* d_out, int out_size) {
    const float* user_embed = (const float*)d_in[0];
    const float* item_embed = (const float*)d_in[1];
    const int*   u_clicks   = (const int*)  d_in[2];
    const int*   v_clicks   = (const int*)  d_in[3];
    const int*   u_buys     = (const int*)  d_in[4];
    const int*   v_buys     = (const int*)  d_in[5];
    const float* W1_clicks  = (const float*)d_in[6];
    const float* b1_clicks  = (const float*)d_in[7];
    const float* W2_clicks  = (const float*)d_in[8];
    const float* b2_clicks  = (const float*)d_in[9];
    const float* W1_buys    = (const float*)d_in[10];
    const float* b1_buys    = (const float*)d_in[11];
    const float* W2_buys    = (const float*)d_in[12];
    const float* b2_buys    = (const float*)d_in[13];

    const int E = in_sizes[2];
    float* out = (float*)d_out;

    __half* tab = nullptr;
    cudaGetSymbolAddress((void**)&tab, g_tab);
    __half* Pc = tab;
    __half* Qc = Pc + P_ELEMS;
    __half* Pb = Qc + Q_ELEMS;
    __half* Qb = Pb + P_ELEMS;

    __nv_bfloat16* wext = nullptr;
    cudaGetSymbolAddress((void**)&wext, g_wext);

    static bool attr_set = false;
    if (!attr_set) {
        cudaFuncSetAttribute(gemm_kernel,
                             cudaFuncAttributeMaxDynamicSharedMemorySize, GEMM_SMEM);
        attr_set = true;
    }

    const size_t wstride = (size_t)HID * KEXT;
    convW_kernel<<<dim3(16, 4), 256>>>(W1_clicks, W1_buys, wext);

    const int gU = NTILE_U < 148 ? NTILE_U : 148;
    const int gI = NTILE_I < 148 ? NTILE_I : 148;
    gemm_kernel<<<gU, 512, GEMM_SMEM>>>(user_embed, NTILE_U, NU,
                                        wext + 0 * wstride, wext + 2 * wstride,
                                        b1_clicks, b1_buys, Pc, Pb);
    gemm_kernel<<<gI, 512, GEMM_SMEM>>>(item_embed, NTILE_I, NI,
                                        wext + 1 * wstride, wext + 3 * wstride,
                                        b1_clicks, b1_buys, Qc, Qb);

    const int eblocks = 592;                       // 4 CTAs/SM
    const int wpt = eblocks * 8 / 2;               // 2368 warps per task
    edge_kernel<<<eblocks, 256>>>(u_clicks, v_clicks, u_buys, v_buys,
                                  Pc, Qc, Pb, Qb,
                                  (const float4*)W2_clicks, b2_clicks,
                                  (const float4*)W2_buys, b2_buys,
                                  out, E, wpt);
}

// round 11
// speedup vs baseline: 1.0848x; 1.0848x over previous
#include <cuda_runtime.h>
#include <cuda_bf16.h>
#include <cuda_fp16.h>
#include <cstdint>

#define IN_DIM 128
#define HID    256
#define NU 100000
#define NI 200000
#define NTILE_U ((NU + 127) / 128)   // 782
#define NTILE_I ((NI + 127) / 128)   // 1563
#define KEXT 384                     // B: [Wh ; Wl ; Wh]

#define P_ELEMS (100000u * 256u)
#define Q_ELEMS (200000u * 256u)
__device__ __half g_tab[2u * (P_ELEMS + Q_ELEMS)];
__device__ __align__(16) __nv_bfloat16 g_wext[4][HID * KEXT];

// ---------------------------------------------------------------------------
__device__ __forceinline__ uint32_t smem_u32(const void* p) {
    uint32_t a;
    asm("{ .reg .u64 t; cvta.to.shared.u64 t, %1; cvt.u32.u64 %0, t; }"
        : "=r"(a) : "l"(p));
    return a;
}
__device__ __forceinline__ uint32_t swz(uint32_t o) { return o ^ ((o >> 3) & 0x70); }
__device__ __forceinline__ uint32_t pack2(float a, float b) {
    __nv_bfloat162 t = __floats2bfloat162_rn(a, b);
    return *(uint32_t*)&t;
}
template <int N>
__device__ __forceinline__ void cpwait() {
    asm volatile("cp.async.wait_group %0;" :: "n"(N) : "memory");
}

// ---------------------------------------------------------------------------
// convW (4 combos in one launch): W-half [128 k][256 n] -> [Wh | Wl | Wh]
// ---------------------------------------------------------------------------
__global__ __launch_bounds__(256)
void convW_kernel(const float* __restrict__ Wc, const float* __restrict__ Wb,
                  __nv_bfloat16* __restrict__ wext) {
    const int combo = blockIdx.y;
    const float* Wsrc = ((combo < 2) ? Wc : Wb) + (size_t)(combo & 1) * IN_DIM * HID;
    __nv_bfloat16* Wext = wext + (size_t)combo * HID * KEXT;
    for (int idx = blockIdx.x * 256 + threadIdx.x; idx < HID * IN_DIM;
         idx += gridDim.x * 256) {
        const int n = idx >> 7, k = idx & 127;
        const float x = Wsrc[(size_t)k * HID + n];
        const __nv_bfloat16 h = __float2bfloat16_rn(x);
        const float l = x - __bfloat162float(h);
        __nv_bfloat16* row = Wext + (size_t)n * KEXT;
        row[k]       = h;
        row[128 + k] = __float2bfloat16_rn(l);
        row[256 + k] = h;
    }
}

// ---------------------------------------------------------------------------
// persistent fused gemm (R9 schedule): fp32 A staged + full tile-top
// conversion to [Ah|Al]; A prefetch at it==0; B double-buffered.
// smem: Astage 64KB | Aconv 64KB | B0 32KB | B1 32KB = 192KB.
// ---------------------------------------------------------------------------
#define KC 64
#define SM_STAGE 0
#define SM_ACONV 65536
#define SM_B_OFF (2 * 65536)
#define GEMM_SMEM (SM_B_OFF + 2 * 32768)

__device__ __forceinline__ void ldsm4(uint32_t* r, uint32_t a) {
    asm volatile("ldmatrix.sync.aligned.m8n8.x4.shared.b16 {%0,%1,%2,%3}, [%4];"
                 : "=r"(r[0]), "=r"(r[1]), "=r"(r[2]), "=r"(r[3]) : "r"(a));
}
__device__ __forceinline__ void mma16816(float* d, const uint32_t* a, const uint32_t* b) {
    asm volatile("mma.sync.aligned.m16n8k16.row.col.f32.bf16.bf16.f32 "
                 "{%0,%1,%2,%3}, {%4,%5,%6,%7}, {%8,%9}, {%0,%1,%2,%3};"
                 : "+f"(d[0]), "+f"(d[1]), "+f"(d[2]), "+f"(d[3])
                 : "r"(a[0]), "r"(a[1]), "r"(a[2]), "r"(a[3]), "r"(b[0]), "r"(b[1]));
}

__global__ __launch_bounds__(512, 1)
void gemm_kernel(const float* __restrict__ A, int ntiles, int N,
                 const __nv_bfloat16* __restrict__ W0,
                 const __nv_bfloat16* __restrict__ W1,
                 const float* __restrict__ b1_0, const float* __restrict__ b1_1,
                 __half* __restrict__ P0, __half* __restrict__ P1) {
    extern __shared__ __align__(1024) unsigned char sm[];
    const uint32_t sbase = smem_u32(sm);
    const int tid  = threadIdx.x;
    const int lane = tid & 31;
    const int wid  = tid >> 5;
    const int wm   = wid & 3;
    const int wn   = wid >> 2;

    auto issue_b = [&](int it) {
        const char* Bb = (const char*)((it < 6) ? W0 : W1);
        const int c = it % 6;
        const uint32_t sb = sbase + SM_B_OFF + (uint32_t)(it & 1) * 32768;
        #pragma unroll
        for (int i = 0; i < 4; i++) {
            const int idx = tid + i * 512;
            const int r = idx >> 3, s = idx & 7;
            const size_t go = (size_t)r * (KEXT * 2) + c * (KC * 2) + s * 16;
            const uint32_t so = swz((uint32_t)(r * 128 + s * 16));
            asm volatile("cp.async.cg.shared.global [%0], [%1], 16;"
                         :: "r"(sb + so), "l"(Bb + go) : "memory");
        }
        asm volatile("cp.async.commit_group;" ::: "memory");
    };
    auto issue_a = [&](int t) {
        const float* Ab = A + (size_t)t * 128 * IN_DIM;
        const uint32_t sa = sbase + SM_STAGE;
        #pragma unroll
        for (int i = 0; i < 8; i++) {
            const int idx = tid + i * 512;
            const int r = idx >> 5, s = idx & 31;
            const int rg = t * 128 + r;
            const uint32_t so = (uint32_t)(r * 512 + s * 16);
            if (rg < N) {
                asm volatile("cp.async.cg.shared.global [%0], [%1], 16;"
                             :: "r"(sa + so), "l"((const char*)Ab + (size_t)r * 512 + s * 16)
                             : "memory");
            } else {
                *(uint4*)(sm + SM_STAGE + so) = make_uint4(0, 0, 0, 0);
            }
        }
        asm volatile("cp.async.commit_group;" ::: "memory");
    };
    auto convert_a = [&]() {
        #pragma unroll
        for (int i = 0; i < 8; i++) {
            const int idx = tid + i * 512;
            const int r = idx >> 5, c4 = idx & 31;
            float4 v = *(float4*)(sm + SM_STAGE + r * 512 + c4 * 16);
            float h0 = __bfloat162float(__float2bfloat16_rn(v.x));
            float h1 = __bfloat162float(__float2bfloat16_rn(v.y));
            float h2 = __bfloat162float(__float2bfloat16_rn(v.z));
            float h3 = __bfloat162float(__float2bfloat16_rn(v.w));
            uint2 uh = { pack2(h0, h1), pack2(h2, h3) };
            uint2 ul = { pack2(v.x - h0, v.y - h1), pack2(v.z - h2, v.w - h3) };
            const uint32_t ck = (uint32_t)(c4 >> 4);
            const uint32_t off = swz((uint32_t)(r * 128 + (c4 & 15) * 8));
            *(uint2*)(sm + SM_ACONV + ck * 16384 + off)         = uh;
            *(uint2*)(sm + SM_ACONV + 32768 + ck * 16384 + off) = ul;
        }
    };

    float acc[2][8][4];
    #pragma unroll
    for (int mt = 0; mt < 2; mt++)
        #pragma unroll
        for (int nt = 0; nt < 8; nt++)
            #pragma unroll
            for (int j = 0; j < 4; j++) acc[mt][nt][j] = 0.f;

    const int t0 = blockIdx.x;
    if (t0 >= ntiles) return;

    issue_a(t0);
    issue_b(0);

    const int amap[6] = {0, 1, 0, 1, 2, 3};

    for (int t = t0; t < ntiles; t += gridDim.x) {
        const int tnext = t + gridDim.x;
        const bool a_iss = (tnext < ntiles);

        cpwait<1>();
        __syncthreads();
        convert_a();
        __syncthreads();

        #pragma unroll
        for (int it = 0; it < 12; it++) {
            const bool last_all = (it == 11) && !a_iss;
            if (!last_all) issue_b((it + 1) % 12);
            if (it == 0 && a_iss) issue_a(tnext);

            if (last_all)                cpwait<0>();
            else if (it < 2 && a_iss)    cpwait<2>();
            else                         cpwait<1>();
            __syncthreads();

            const uint32_t sa = sbase + SM_ACONV + (uint32_t)(amap[it % 6] * 16384);
            const uint32_t sb = sbase + SM_B_OFF + (uint32_t)(it & 1) * 32768;

            #pragma unroll
            for (int ks = 0; ks < KC / 16; ks++) {
                uint32_t af[2][4];
                #pragma unroll
                for (int mt = 0; mt < 2; mt++) {
                    const int row = wm * 32 + mt * 16 + (lane & 15);
                    const uint32_t off = (uint32_t)(row * 128 + ks * 32 + (lane >> 4) * 16);
                    ldsm4(af[mt], sa + swz(off));
                }
                uint32_t bfr[8][2];
                #pragma unroll
                for (int ntp = 0; ntp < 4; ntp++) {
                    const int nrow = wn * 64 + ntp * 16 + ((lane >> 4) << 3) + (lane & 7);
                    const uint32_t off = (uint32_t)(nrow * 128 + ks * 32 + ((lane >> 3) & 1) * 16);
                    uint32_t r4[4];
                    ldsm4(r4, sb + swz(off));
                    bfr[2 * ntp][0] = r4[0]; bfr[2 * ntp][1] = r4[1];
                    bfr[2 * ntp + 1][0] = r4[2]; bfr[2 * ntp + 1][1] = r4[3];
                }
                #pragma unroll
                for (int mt = 0; mt < 2; mt++)
                    #pragma unroll
                    for (int nt = 0; nt < 8; nt++)
                        mma16816(acc[mt][nt], af[mt], bfr[nt]);
            }
            __syncthreads();

            if (it == 5 || it == 11) {
                __half* Pt = (it == 5) ? P0 : P1;
                const float* b1 = (it == 5) ? b1_0 : b1_1;
                const int rb = t * 128 + wm * 32 + (lane >> 2);
                const int cb = wn * 64 + (lane & 3) * 2;
                #pragma unroll
                for (int mt = 0; mt < 2; mt++) {
                    #pragma unroll
                    for (int hf = 0; hf < 2; hf++) {
                        const int r = rb + mt * 16 + hf * 8;
                        if (r < N) {
                            __half* dst = Pt + (size_t)r * HID + cb;
                            #pragma unroll
                            for (int nt = 0; nt < 8; nt++) {
                                const int c = cb + nt * 8;
                                float a0 = acc[mt][nt][hf * 2]     + __ldg(b1 + c);
                                float a1 = acc[mt][nt][hf * 2 + 1] + __ldg(b1 + c + 1);
                                *(__half2*)(dst + nt * 8) = __floats2half2_rn(a0, a1);
                            }
                        }
                    }
                }
                #pragma unroll
                for (int mt = 0; mt < 2; mt++)
                    #pragma unroll
                    for (int nt = 0; nt < 8; nt++)
                        #pragma unroll
                        for (int j = 0; j < 4; j++) acc[mt][nt][j] = 0.f;
            }
        }
    }
}

// ---------------------------------------------------------------------------
// edge: persistent warps; W2/b2 in registers; 2 edges in flight per warp.
// ---------------------------------------------------------------------------
__global__ __launch_bounds__(256)
void edge_kernel(const int* __restrict__ uc, const int* __restrict__ vc,
                 const int* __restrict__ ub, const int* __restrict__ vb,
                 const __half* __restrict__ Pc, const __half* __restrict__ Qc,
                 const __half* __restrict__ Pb, const __half* __restrict__ Qb,
                 const float4* __restrict__ W2c, const float* __restrict__ b2c,
                 const float4* __restrict__ W2b, const float* __restrict__ b2b,
                 float* __restrict__ out, int E, int wpt) {
    const int gw   = (blockIdx.x * blockDim.x + threadIdx.x) >> 5;
    const int lane = threadIdx.x & 31;
    const bool buys = (gw >= wpt);
    const int w0 = buys ? gw - wpt : gw;

    const int* uu = buys ? ub : uc;
    const int* vv = buys ? vb : vc;
    const __half* P = buys ? Pb : Pc;
    const __half* Q = buys ? Qb : Qc;
    const float4* W2 = buys ? W2b : W2c;
    float* o = out + (buys ? E : 0);

    float4 wv0 = __ldg(W2 + lane * 2);
    float4 wv1 = __ldg(W2 + lane * 2 + 1);
    const float b2v = __ldg(buys ? b2b : b2c);
    float w[8] = { wv0.x, wv0.y, wv0.z, wv0.w, wv1.x, wv1.y, wv1.z, wv1.w };

    auto dot8 = [&](const uint4& pr, const uint4& qr) -> float {
        const __half2* p2 = (const __half2*)&pr;
        const __half2* q2 = (const __half2*)&qr;
        float a = 0.f;
        #pragma unroll
        for (int i = 0; i < 4; i++) {
            float2 pf = __half22float2(p2[i]);
            float2 qf = __half22float2(q2[i]);
            a = fmaf(fmaxf(pf.x + qf.x, 0.f), w[2 * i],     a);
            a = fmaf(fmaxf(pf.y + qf.y, 0.f), w[2 * i + 1], a);
        }
        return a;
    };

    int e = w0;
    for (; e + wpt < E; e += 2 * wpt) {
        const int u0 = __ldg(uu + e),       v0 = __ldg(vv + e);
        const int u1 = __ldg(uu + e + wpt), v1 = __ldg(vv + e + wpt);
        uint4 pr0 = *(const uint4*)(P + (size_t)u0 * HID + lane * 8);
        uint4 qr0 = *(const uint4*)(Q + (size_t)v0 * HID + lane * 8);
        uint4 pr1 = *(const uint4*)(P + (size_t)u1 * HID + lane * 8);
        uint4 qr1 = *(const uint4*)(Q + (size_t)v1 * HID + lane * 8);
        float a0 = dot8(pr0, qr0);
        float a1 = dot8(pr1, qr1);
        #pragma unroll
        for (int off = 16; off; off >>= 1) {
            a0 += __shfl_xor_sync(0xffffffffu, a0, off);
            a1 += __shfl_xor_sync(0xffffffffu, a1, off);
        }
        if (lane == 0) { o[e] = a0 + b2v; o[e + wpt] = a1 + b2v; }
    }
    if (e < E) {
        const int u0 = __ldg(uu + e), v0 = __ldg(vv + e);
        uint4 pr0 = *(const uint4*)(P + (size_t)u0 * HID + lane * 8);
        uint4 qr0 = *(const uint4*)(Q + (size_t)v0 * HID + lane * 8);
        float a0 = dot8(pr0, qr0);
        #pragma unroll
        for (int off = 16; off; off >>= 1)
            a0 += __shfl_xor_sync(0xffffffffu, a0, off);
        if (lane == 0) o[e] = a0 + b2v;
    }
}

// ---------------------------------------------------------------------------
extern "C" void kernel_launch(void* const* d_in, const int* in_sizes, int n_in,
                              void* d_out, int out_size) {
    const float* user_embed = (const float*)d_in[0];
    const float* item_embed = (const float*)d_in[1];
    const int*   u_clicks   = (const int*)  d_in[2];
    const int*   v_clicks   = (const int*)  d_in[3];
    const int*   u_buys     = (const int*)  d_in[4];
    const int*   v_buys     = (const int*)  d_in[5];
    const float* W1_clicks  = (const float*)d_in[6];
    const float* b1_clicks  = (const float*)d_in[7];
    const float* W2_clicks  = (const float*)d_in[8];
    const float* b2_clicks  = (const float*)d_in[9];
    const float* W1_buys    = (const float*)d_in[10];
    const float* b1_buys    = (const float*)d_in[11];
    const float* W2_buys    = (const float*)d_in[12];
    const float* b2_buys    = (const float*)d_in[13];

    const int E = in_sizes[2];
    float* out = (float*)d_out;

    __half* tab = nullptr;
    cudaGetSymbolAddress((void**)&tab, g_tab);
    __half* Pc = tab;
    __half* Qc = Pc + P_ELEMS;
    __half* Pb = Qc + Q_ELEMS;
    __half* Qb = Pb + P_ELEMS;

    __nv_bfloat16* wext = nullptr;
    cudaGetSymbolAddress((void**)&wext, g_wext);

    static bool attr_set = false;
    if (!attr_set) {
        cudaFuncSetAttribute(gemm_kernel,
                             cudaFuncAttributeMaxDynamicSharedMemorySize, GEMM_SMEM);
        attr_set = true;
    }

    const size_t wstride = (size_t)HID * KEXT;
    convW_kernel<<<dim3(16, 4), 256>>>(W1_clicks, W1_buys, wext);

    const int gU = NTILE_U < 148 ? NTILE_U : 148;
    const int gI = NTILE_I < 148 ? NTILE_I : 148;
    gemm_kernel<<<gU, 512, GEMM_SMEM>>>(user_embed, NTILE_U, NU,
                                        wext + 0 * wstride, wext + 2 * wstride,
                                        b1_clicks, b1_buys, Pc, Pb);
    gemm_kernel<<<gI, 512, GEMM_SMEM>>>(item_embed, NTILE_I, NI,
                                        wext + 1 * wstride, wext + 3 * wstride,
                                        b1_clicks, b1_buys, Qc, Qb);

    const int eblocks = 740;                       // 5 CTAs/SM (regs allow 5)
    const int wpt = eblocks * 8 / 2;               // 2960 warps per task
    edge_kernel<<<eblocks, 256>>>(u_clicks, v_clicks, u_buys, v_buys,
                                  Pc, Qc, Pb, Qb,
                                  (const float4*)W2_clicks, b2_clicks,
                                  (const float4*)W2_buys, b2_buys,
                                  out, E, wpt);
}